// round 15
// baseline (speedup 1.0000x reference)
#include <cuda_runtime.h>
#include <cstdint>

#define T_TOK 4096
#define D_DIM 2048
#define N_EXP 64
#define TOPK  2
#define CAP   160
#define TEC   (T_TOK * N_EXP * CAP)   // 41,943,040

#define KSPLIT 4
#define KQ    (D_DIM / KSPLIT)        // 512
#define BT    64                      // tokens per CTA
#define BK    32                      // K per tile
#define XP    68                      // smem row stride (floats)
#define NTILE (KQ / BK)               // 16
#define GEMM_BLOCKS (T_TOK / BT * KSPLIT)   // 256

#define FILL_CHUNK  32768
#define FILL_BLOCKS 512               // 10240 chunks / 512 = 20 each (exact)

#define TILE_FLOATS (2 * BK * XP)     // xsT+wsT per buffer: 4352 floats
#define SMEM_FLOATS (2 * TILE_FLOATS) // double buffer: 8704 floats (34816 B)

// scratch (device globals; no allocation allowed)
__device__ int   g_te[T_TOK * TOPK];
__device__ float g_tw[T_TOK * TOPK];
__device__ float g_part[KSPLIT][T_TOK][N_EXP];   // partial logits (4 MB)

__device__ __forceinline__ void ffma2(unsigned long long& d,
                                      unsigned long long a, unsigned long long b)
{
    asm("fma.rn.f32x2 %0, %1, %2, %0;" : "+l"(d) : "l"(a), "l"(b));
}
__device__ __forceinline__ unsigned long long dup2(float v)
{
    unsigned long long r;
    unsigned u = __float_as_uint(v);
    asm("mov.b64 %0, {%1, %1};" : "=l"(r) : "r"(u));
    return r;
}
__device__ __forceinline__ float lo32(unsigned long long a)
{ return __uint_as_float((unsigned)a); }
__device__ __forceinline__ float hi32(unsigned long long a)
{ return __uint_as_float((unsigned)(a >> 32)); }

// ---------------- Kernel A: fused TMA fill + K-split f32x2 GEMM -------------
__global__ void __launch_bounds__(256) gemm_fill_kernel(
    const float* __restrict__ x, const float* __restrict__ wg,
    float* __restrict__ out, int out_size)
{
    __shared__ __align__(1024) float smbuf[SMEM_FLOATS];   // 34.8 KB union

    if (blockIdx.x < FILL_BLOCKS) {
        // ---- TMA bulk-store fill role ----
        float4* zb = (float4*)smbuf;
        for (int i = threadIdx.x; i < FILL_CHUNK / 16; i += 256)
            zb[i] = make_float4(0.f, 0.f, 0.f, 0.f);
        __syncthreads();
        asm volatile("fence.proxy.async.shared::cta;" ::: "memory");

        size_t   bytes = (size_t)out_size * sizeof(float);
        unsigned nch   = (unsigned)(bytes / FILL_CHUNK);
        uint32_t saddr = (uint32_t)__cvta_generic_to_shared(smbuf);

        if (threadIdx.x == 0) {
            for (unsigned c = blockIdx.x; c < nch; c += FILL_BLOCKS) {
                char* dst = (char*)out + (size_t)c * FILL_CHUNK;
                asm volatile(
                    "cp.async.bulk.global.shared::cta.bulk_group [%0], [%1], %2;"
                    :: "l"(dst), "r"(saddr), "r"((unsigned)FILL_CHUNK) : "memory");
            }
            asm volatile("cp.async.bulk.commit_group;" ::: "memory");
            asm volatile("cp.async.bulk.wait_group 0;" ::: "memory");
        }
        size_t tail = bytes % FILL_CHUNK;
        if (tail && blockIdx.x == 0) {
            char* p = (char*)out + bytes - tail;
            for (size_t i = threadIdx.x * 4; i + 3 < tail; i += 1024)
                *(float*)(p + i) = 0.f;
        }
        return;
    }

    // ---- GEMM role: 64 tokens x 64 experts, K-slice of 512, double-buffered ----
    int bid   = blockIdx.x - FILL_BLOCKS;
    int tid   = threadIdx.x;
    int kq    = bid & (KSPLIT - 1);
    int tok0  = (bid >> 2) * BT;
    int kbase = kq * KQ;

    int r = tid >> 2;                // 0..63: token row / expert row
    int c = tid & 3;                 // float4 column group

    const float* xptr = x  + (size_t)(tok0 + r) * D_DIM + kbase;
    const float* wptr = wg + (size_t)r          * D_DIM + kbase;

    unsigned long long acc[4][2];
#pragma unroll
    for (int i = 0; i < 4; i++) { acc[i][0] = 0ull; acc[i][1] = 0ull; }

    int txx = tid & 15;              // expert group: 4*txx
    int tyy = tid >> 4;              // token group:  4*tyy

    // preload + store tile 0 into buffer 0
    float4 a0 = *(const float4*)(xptr + 4 * c);
    float4 a1 = *(const float4*)(xptr + 16 + 4 * c);
    float4 b0 = *(const float4*)(wptr + 4 * c);
    float4 b1 = *(const float4*)(wptr + 16 + 4 * c);
    {
        float* xsT = smbuf;
        float* wsT = smbuf + BK * XP;
        xsT[(4 * c + 0) * XP + r] = a0.x;
        xsT[(4 * c + 1) * XP + r] = a0.y;
        xsT[(4 * c + 2) * XP + r] = a0.z;
        xsT[(4 * c + 3) * XP + r] = a0.w;
        xsT[(4 * c + 16) * XP + r] = a1.x;
        xsT[(4 * c + 17) * XP + r] = a1.y;
        xsT[(4 * c + 18) * XP + r] = a1.z;
        xsT[(4 * c + 19) * XP + r] = a1.w;
        wsT[(4 * c + 0) * XP + r] = b0.x;
        wsT[(4 * c + 1) * XP + r] = b0.y;
        wsT[(4 * c + 2) * XP + r] = b0.z;
        wsT[(4 * c + 3) * XP + r] = b0.w;
        wsT[(4 * c + 16) * XP + r] = b1.x;
        wsT[(4 * c + 17) * XP + r] = b1.y;
        wsT[(4 * c + 18) * XP + r] = b1.z;
        wsT[(4 * c + 19) * XP + r] = b1.w;
    }
    __syncthreads();

#pragma unroll 1
    for (int t = 0; t < NTILE; t++) {
        // prefetch next tile into registers (hidden under compute)
        if (t + 1 < NTILE) {
            int off = (t + 1) * BK;
            a0 = *(const float4*)(xptr + off + 4 * c);
            a1 = *(const float4*)(xptr + off + 16 + 4 * c);
            b0 = *(const float4*)(wptr + off + 4 * c);
            b1 = *(const float4*)(wptr + off + 16 + 4 * c);
        }

        // compute tile t from buffer t&1
        const float* xsT = smbuf + (t & 1) * TILE_FLOATS;
        const float* wsT = xsT + BK * XP;
#pragma unroll
        for (int kk = 0; kk < BK; kk++) {
            float4 xv = *(const float4*)&xsT[kk * XP + 4 * tyy];
            ulonglong2 wp = *(const ulonglong2*)&wsT[kk * XP + 4 * txx];
            unsigned long long x0 = dup2(xv.x), x1 = dup2(xv.y);
            unsigned long long x2 = dup2(xv.z), x3 = dup2(xv.w);
            ffma2(acc[0][0], x0, wp.x); ffma2(acc[0][1], x0, wp.y);
            ffma2(acc[1][0], x1, wp.x); ffma2(acc[1][1], x1, wp.y);
            ffma2(acc[2][0], x2, wp.x); ffma2(acc[2][1], x2, wp.y);
            ffma2(acc[3][0], x3, wp.x); ffma2(acc[3][1], x3, wp.y);
        }

        // store prefetched tile t+1 into the other buffer, then one sync
        if (t + 1 < NTILE) {
            float* xsN = smbuf + ((t + 1) & 1) * TILE_FLOATS;
            float* wsN = xsN + BK * XP;
            xsN[(4 * c + 0) * XP + r] = a0.x;
            xsN[(4 * c + 1) * XP + r] = a0.y;
            xsN[(4 * c + 2) * XP + r] = a0.z;
            xsN[(4 * c + 3) * XP + r] = a0.w;
            xsN[(4 * c + 16) * XP + r] = a1.x;
            xsN[(4 * c + 17) * XP + r] = a1.y;
            xsN[(4 * c + 18) * XP + r] = a1.z;
            xsN[(4 * c + 19) * XP + r] = a1.w;
            wsN[(4 * c + 0) * XP + r] = b0.x;
            wsN[(4 * c + 1) * XP + r] = b0.y;
            wsN[(4 * c + 2) * XP + r] = b0.z;
            wsN[(4 * c + 3) * XP + r] = b0.w;
            wsN[(4 * c + 16) * XP + r] = b1.x;
            wsN[(4 * c + 17) * XP + r] = b1.y;
            wsN[(4 * c + 18) * XP + r] = b1.z;
            wsN[(4 * c + 19) * XP + r] = b1.w;
            __syncthreads();
        }
    }

    // epilogue: write partial logits (coalesced float4)
#pragma unroll
    for (int i = 0; i < 4; i++) {
        *(float4*)&g_part[kq][tok0 + 4 * tyy + i][4 * txx] =
            make_float4(lo32(acc[i][0]), hi32(acc[i][0]),
                        lo32(acc[i][1]), hi32(acc[i][1]));
    }
}

// ---------------- Kernel B: sum 4 K-parts + top2 + softmax ------------------
__global__ void __launch_bounds__(64) top2_kernel()
{
    int t = blockIdx.x * 64 + threadIdx.x;     // token id

    const float4* p0 = (const float4*)&g_part[0][t][0];
    const float4* p1 = (const float4*)&g_part[1][t][0];
    const float4* p2 = (const float4*)&g_part[2][t][0];
    const float4* p3 = (const float4*)&g_part[3][t][0];

    float v0 = -3.4e38f, v1 = -3.4e38f;
    int e0 = 0, e1 = 0;
#pragma unroll
    for (int i = 0; i < N_EXP / 4; i++) {
        float4 a = p0[i], b = p1[i], cc = p2[i], d = p3[i];
        float s[4] = { ((a.x + b.x) + cc.x) + d.x,
                       ((a.y + b.y) + cc.y) + d.y,
                       ((a.z + b.z) + cc.z) + d.z,
                       ((a.w + b.w) + cc.w) + d.w };
#pragma unroll
        for (int j = 0; j < 4; j++) {
            float v = s[j];
            int   e = 4 * i + j;
            if (v > v0)      { v1 = v0; e1 = e0; v0 = v; e0 = e; }
            else if (v > v1) { v1 = v;  e1 = e; }
        }
    }
    float rr = expf(v1 - v0);
    float q0 = 1.f / (1.f + rr);
    float q1 = rr * q0;
    g_te[2 * t]     = e0;
    g_te[2 * t + 1] = e1;
    g_tw[2 * t]     = q0;
    g_tw[2 * t + 1] = q1;
}

// ---------------- Kernel C: order-exact capacity assignment -----------------
__global__ void __launch_bounds__(256) assign_kernel(float* __restrict__ out)
{
    int e    = blockIdx.x;            // expert 0..63
    int tid  = threadIdx.x;
    int lane = tid & 31;
    int wid  = tid >> 5;

    int ids[32];
    const int4* te4 = (const int4*)g_te;
#pragma unroll
    for (int k = 0; k < 8; k++) {
        int4 v = te4[tid * 8 + k];
        ids[4 * k + 0] = v.x; ids[4 * k + 1] = v.y;
        ids[4 * k + 2] = v.z; ids[4 * k + 3] = v.w;
    }

    int cnt = 0;
#pragma unroll
    for (int k = 0; k < 32; k++) cnt += (ids[k] == e);

    int c = cnt;
#pragma unroll
    for (int o = 1; o < 32; o <<= 1) {
        int n = __shfl_up_sync(0xffffffffu, c, o);
        if (lane >= o) c += n;
    }
    __shared__ int wsum[8];
    if (lane == 31) wsum[wid] = c;
    __syncthreads();
    if (wid == 0 && lane < 8) {
        int v = wsum[lane];
#pragma unroll
        for (int o = 1; o < 8; o <<= 1) {
            int n = __shfl_up_sync(0xffu, v, o);
            if (lane >= o) v += n;
        }
        wsum[lane] = v;
    }
    __syncthreads();
    int prefix = c - cnt + (wid ? wsum[wid - 1] : 0);
    int total  = wsum[7];

    float* cb = out + N_EXP;
    float* mk = out + N_EXP + TEC;
    int slot = prefix;
#pragma unroll
    for (int k = 0; k < 32; k++) {
        if (ids[k] == e) {
            if (slot < CAP) {
                int a = tid * 32 + k;
                int t = a >> 1;
                size_t idx = (size_t)t * (N_EXP * CAP) + (size_t)e * CAP + slot;
                cb[idx] = g_tw[a];
                mk[idx] = 1.0f;
            }
            slot++;
        }
    }

    if (tid == 0)
        out[e] = (float)(total < CAP ? total : CAP);
}

extern "C" void kernel_launch(void* const* d_in, const int* in_sizes, int n_in,
                              void* d_out, int out_size)
{
    const float* x  = (const float*)d_in[0];
    const float* wg = (const float*)d_in[1];
    float* out = (float*)d_out;

    gemm_fill_kernel<<<FILL_BLOCKS + GEMM_BLOCKS, 256>>>(x, wg, out, out_size);
    top2_kernel<<<T_TOK / 64, 64>>>();
    assign_kernel<<<N_EXP, 256>>>(out);
}

// round 16
// speedup vs baseline: 1.1582x; 1.1582x over previous
#include <cuda_runtime.h>
#include <cstdint>

#define T_TOK 4096
#define D_DIM 2048
#define N_EXP 64
#define TOPK  2
#define CAP   160
#define TEC   (T_TOK * N_EXP * CAP)   // 41,943,040

#define KSPLIT 8
#define KQ    (D_DIM / KSPLIT)        // 256
#define BT    64                      // tokens per CTA
#define BK    32                      // K per tile
#define XP    68                      // smem row stride (floats)
#define NTILE (KQ / BK)               // 8
#define GEMM_BLOCKS (T_TOK / BT * KSPLIT)   // 512

#define FILL_CHUNK  16384
#define FILL_BLOCKS 320               // 20480 chunks / 320 = 64 each (exact)

#define TILE_FLOATS (2 * BK * XP)     // xsT+wsT: 4352 floats = 17408 B (union >= fill 16384)

// scratch (device globals; no allocation allowed)
__device__ int   g_te[T_TOK * TOPK];
__device__ float g_tw[T_TOK * TOPK];
__device__ float g_part[KSPLIT][T_TOK][N_EXP];   // partial logits (8 MB)

__device__ __forceinline__ void ffma2(unsigned long long& d,
                                      unsigned long long a, unsigned long long b)
{
    asm("fma.rn.f32x2 %0, %1, %2, %0;" : "+l"(d) : "l"(a), "l"(b));
}
__device__ __forceinline__ unsigned long long dup2(float v)
{
    unsigned long long r;
    unsigned u = __float_as_uint(v);
    asm("mov.b64 %0, {%1, %1};" : "=l"(r) : "r"(u));
    return r;
}
__device__ __forceinline__ float lo32(unsigned long long a)
{ return __uint_as_float((unsigned)a); }
__device__ __forceinline__ float hi32(unsigned long long a)
{ return __uint_as_float((unsigned)(a >> 32)); }

// ---------------- Kernel A: fused TMA fill + K-split f32x2 GEMM -------------
__global__ void __launch_bounds__(256) gemm_fill_kernel(
    const float* __restrict__ x, const float* __restrict__ wg,
    float* __restrict__ out, int out_size)
{
    __shared__ __align__(1024) float smbuf[TILE_FLOATS];   // 17.4 KB union

    if (blockIdx.x < FILL_BLOCKS) {
        // ---- TMA bulk-store fill role ----
        float4* zb = (float4*)smbuf;
        for (int i = threadIdx.x; i < FILL_CHUNK / 16; i += 256)
            zb[i] = make_float4(0.f, 0.f, 0.f, 0.f);
        __syncthreads();
        asm volatile("fence.proxy.async.shared::cta;" ::: "memory");

        size_t   bytes = (size_t)out_size * sizeof(float);
        unsigned nch   = (unsigned)(bytes / FILL_CHUNK);
        uint32_t saddr = (uint32_t)__cvta_generic_to_shared(smbuf);

        if (threadIdx.x == 0) {
            for (unsigned c = blockIdx.x; c < nch; c += FILL_BLOCKS) {
                char* dst = (char*)out + (size_t)c * FILL_CHUNK;
                asm volatile(
                    "cp.async.bulk.global.shared::cta.bulk_group [%0], [%1], %2;"
                    :: "l"(dst), "r"(saddr), "r"((unsigned)FILL_CHUNK) : "memory");
            }
            asm volatile("cp.async.bulk.commit_group;" ::: "memory");
            asm volatile("cp.async.bulk.wait_group 0;" ::: "memory");
        }
        size_t tail = bytes % FILL_CHUNK;
        if (tail && blockIdx.x == 0) {
            char* p = (char*)out + bytes - tail;
            for (size_t i = threadIdx.x * 4; i + 3 < tail; i += 1024)
                *(float*)(p + i) = 0.f;
        }
        return;
    }

    // ---- GEMM role: 64 tokens x 64 experts, K-slice of 256 ----
    float* xsT = smbuf;              // [BK][XP] k-major, token minor
    float* wsT = smbuf + BK * XP;    // [BK][XP] k-major, expert minor

    int bid   = blockIdx.x - FILL_BLOCKS;
    int tid   = threadIdx.x;
    int kq    = bid & (KSPLIT - 1);
    int tok0  = (bid >> 3) * BT;
    int kbase = kq * KQ;

    int r = tid >> 2;                // 0..63: token row / expert row
    int c = tid & 3;                 // float4 column group

    const float* xptr = x  + (size_t)(tok0 + r) * D_DIM + kbase;
    const float* wptr = wg + (size_t)r          * D_DIM + kbase;

    unsigned long long acc[4][2];
#pragma unroll
    for (int i = 0; i < 4; i++) { acc[i][0] = 0ull; acc[i][1] = 0ull; }

    int txx = tid & 15;              // expert group: 4*txx
    int tyy = tid >> 4;              // token group:  4*tyy

    // preload tile 0
    float4 a0 = *(const float4*)(xptr + 4 * c);
    float4 a1 = *(const float4*)(xptr + 16 + 4 * c);
    float4 b0 = *(const float4*)(wptr + 4 * c);
    float4 b1 = *(const float4*)(wptr + 16 + 4 * c);

#pragma unroll 1
    for (int t = 0; t < NTILE; t++) {
        // store current tile transposed
        xsT[(4 * c + 0) * XP + r] = a0.x;
        xsT[(4 * c + 1) * XP + r] = a0.y;
        xsT[(4 * c + 2) * XP + r] = a0.z;
        xsT[(4 * c + 3) * XP + r] = a0.w;
        xsT[(4 * c + 16) * XP + r] = a1.x;
        xsT[(4 * c + 17) * XP + r] = a1.y;
        xsT[(4 * c + 18) * XP + r] = a1.z;
        xsT[(4 * c + 19) * XP + r] = a1.w;
        wsT[(4 * c + 0) * XP + r] = b0.x;
        wsT[(4 * c + 1) * XP + r] = b0.y;
        wsT[(4 * c + 2) * XP + r] = b0.z;
        wsT[(4 * c + 3) * XP + r] = b0.w;
        wsT[(4 * c + 16) * XP + r] = b1.x;
        wsT[(4 * c + 17) * XP + r] = b1.y;
        wsT[(4 * c + 18) * XP + r] = b1.z;
        wsT[(4 * c + 19) * XP + r] = b1.w;
        __syncthreads();

        // prefetch next tile into registers (latency hidden under compute)
        if (t + 1 < NTILE) {
            int off = (t + 1) * BK;
            a0 = *(const float4*)(xptr + off + 4 * c);
            a1 = *(const float4*)(xptr + off + 16 + 4 * c);
            b0 = *(const float4*)(wptr + off + 4 * c);
            b1 = *(const float4*)(wptr + off + 16 + 4 * c);
        }

        // compute: 32 kk x (4 tok x 4 exp) via packed f32x2
#pragma unroll
        for (int kk = 0; kk < BK; kk++) {
            float4 xv = *(const float4*)&xsT[kk * XP + 4 * tyy];
            ulonglong2 wp = *(const ulonglong2*)&wsT[kk * XP + 4 * txx];
            unsigned long long x0 = dup2(xv.x), x1 = dup2(xv.y);
            unsigned long long x2 = dup2(xv.z), x3 = dup2(xv.w);
            ffma2(acc[0][0], x0, wp.x); ffma2(acc[0][1], x0, wp.y);
            ffma2(acc[1][0], x1, wp.x); ffma2(acc[1][1], x1, wp.y);
            ffma2(acc[2][0], x2, wp.x); ffma2(acc[2][1], x2, wp.y);
            ffma2(acc[3][0], x3, wp.x); ffma2(acc[3][1], x3, wp.y);
        }
        __syncthreads();
    }

    // epilogue: write partial logits (coalesced float4)
#pragma unroll
    for (int i = 0; i < 4; i++) {
        *(float4*)&g_part[kq][tok0 + 4 * tyy + i][4 * txx] =
            make_float4(lo32(acc[i][0]), hi32(acc[i][0]),
                        lo32(acc[i][1]), hi32(acc[i][1]));
    }
}

// ---------------- Kernel B: sum 8 K-parts + top2 + softmax ------------------
__global__ void __launch_bounds__(128) top2_kernel()
{
    int t = blockIdx.x * 128 + threadIdx.x;    // token id

    float v0 = -3.4e38f, v1 = -3.4e38f;
    int e0 = 0, e1 = 0;
#pragma unroll
    for (int i = 0; i < N_EXP / 4; i++) {
        float4 s4 = *(const float4*)&g_part[0][t][4 * i];
        float s[4] = { s4.x, s4.y, s4.z, s4.w };
#pragma unroll
        for (int p = 1; p < KSPLIT; p++) {
            float4 q = *(const float4*)&g_part[p][t][4 * i];
            s[0] += q.x; s[1] += q.y; s[2] += q.z; s[3] += q.w;
        }
#pragma unroll
        for (int j = 0; j < 4; j++) {
            float v = s[j];
            int   e = 4 * i + j;
            if (v > v0)      { v1 = v0; e1 = e0; v0 = v; e0 = e; }
            else if (v > v1) { v1 = v;  e1 = e; }
        }
    }
    float rr = expf(v1 - v0);
    float q0 = 1.f / (1.f + rr);
    float q1 = rr * q0;
    g_te[2 * t]     = e0;
    g_te[2 * t + 1] = e1;
    g_tw[2 * t]     = q0;
    g_tw[2 * t + 1] = q1;
}

// ---------------- Kernel C: order-exact capacity assignment -----------------
__global__ void __launch_bounds__(256) assign_kernel(float* __restrict__ out)
{
    int e    = blockIdx.x;            // expert 0..63
    int tid  = threadIdx.x;
    int lane = tid & 31;
    int wid  = tid >> 5;

    int ids[32];
    const int4* te4 = (const int4*)g_te;
#pragma unroll
    for (int k = 0; k < 8; k++) {
        int4 v = te4[tid * 8 + k];
        ids[4 * k + 0] = v.x; ids[4 * k + 1] = v.y;
        ids[4 * k + 2] = v.z; ids[4 * k + 3] = v.w;
    }

    int cnt = 0;
#pragma unroll
    for (int k = 0; k < 32; k++) cnt += (ids[k] == e);

    int c = cnt;
#pragma unroll
    for (int o = 1; o < 32; o <<= 1) {
        int n = __shfl_up_sync(0xffffffffu, c, o);
        if (lane >= o) c += n;
    }
    __shared__ int wsum[8];
    if (lane == 31) wsum[wid] = c;
    __syncthreads();
    if (wid == 0 && lane < 8) {
        int v = wsum[lane];
#pragma unroll
        for (int o = 1; o < 8; o <<= 1) {
            int n = __shfl_up_sync(0xffu, v, o);
            if (lane >= o) v += n;
        }
        wsum[lane] = v;
    }
    __syncthreads();
    int prefix = c - cnt + (wid ? wsum[wid - 1] : 0);
    int total  = wsum[7];

    float* cb = out + N_EXP;
    float* mk = out + N_EXP + TEC;
    int slot = prefix;
#pragma unroll
    for (int k = 0; k < 32; k++) {
        if (ids[k] == e) {
            if (slot < CAP) {
                int a = tid * 32 + k;
                int t = a >> 1;
                size_t idx = (size_t)t * (N_EXP * CAP) + (size_t)e * CAP + slot;
                cb[idx] = g_tw[a];
                mk[idx] = 1.0f;
            }
            slot++;
        }
    }

    if (tid == 0)
        out[e] = (float)(total < CAP ? total : CAP);
}

extern "C" void kernel_launch(void* const* d_in, const int* in_sizes, int n_in,
                              void* d_out, int out_size)
{
    const float* x  = (const float*)d_in[0];
    const float* wg = (const float*)d_in[1];
    float* out = (float*)d_out;

    gemm_fill_kernel<<<FILL_BLOCKS + GEMM_BLOCKS, 256>>>(x, wg, out, out_size);
    top2_kernel<<<T_TOK / 128, 128>>>();
    assign_kernel<<<N_EXP, 256>>>(out);
}

// round 17
// speedup vs baseline: 1.3376x; 1.1550x over previous
#include <cuda_runtime.h>
#include <cstdint>

#define T_TOK 4096
#define D_DIM 2048
#define N_EXP 64
#define TOPK  2
#define CAP   160
#define TEC   (T_TOK * N_EXP * CAP)   // 41,943,040

#define KSPLIT 4
#define KQ    (D_DIM / KSPLIT)        // 512
#define BT    64                      // tokens per CTA
#define BK    32                      // K per tile
#define XP    68                      // smem row stride (floats)
#define NTILE (KQ / BK)               // 16
#define GEMM_BLOCKS (T_TOK / BT * KSPLIT)   // 256

#define FILL_CHUNK  16384
#define FILL_BLOCKS 320               // 20480 chunks / 320 = 64 each (exact)

#define TILE_FLOATS (2 * BK * XP)     // 4352 floats = 17408 B (union >= 16384)

// scratch (device globals; no allocation allowed)
__device__ int   g_te[T_TOK * TOPK];
__device__ float g_tw[T_TOK * TOPK];
__device__ float g_part[T_TOK][KSPLIT][N_EXP];   // token-contiguous partials (4 MB)

__device__ __forceinline__ void ffma2(unsigned long long& d,
                                      unsigned long long a, unsigned long long b)
{
    asm("fma.rn.f32x2 %0, %1, %2, %0;" : "+l"(d) : "l"(a), "l"(b));
}
__device__ __forceinline__ unsigned long long dup2(float v)
{
    unsigned long long r;
    unsigned u = __float_as_uint(v);
    asm("mov.b64 %0, {%1, %1};" : "=l"(r) : "r"(u));
    return r;
}
__device__ __forceinline__ float lo32(unsigned long long a)
{ return __uint_as_float((unsigned)a); }
__device__ __forceinline__ float hi32(unsigned long long a)
{ return __uint_as_float((unsigned)(a >> 32)); }

// ---------------- Kernel A: fused TMA fill + K-split f32x2 GEMM -------------
__global__ void __launch_bounds__(256) gemm_fill_kernel(
    const float* __restrict__ x, const float* __restrict__ wg,
    float* __restrict__ out, int out_size)
{
    __shared__ __align__(1024) float smbuf[TILE_FLOATS];   // 17.4 KB union

    if (blockIdx.x < FILL_BLOCKS) {
        // ---- TMA bulk-store fill role (evict_first: don't churn L2) ----
        float4* zb = (float4*)smbuf;
        for (int i = threadIdx.x; i < FILL_CHUNK / 16; i += 256)
            zb[i] = make_float4(0.f, 0.f, 0.f, 0.f);
        __syncthreads();
        asm volatile("fence.proxy.async.shared::cta;" ::: "memory");

        size_t   bytes = (size_t)out_size * sizeof(float);
        unsigned nch   = (unsigned)(bytes / FILL_CHUNK);
        uint32_t saddr = (uint32_t)__cvta_generic_to_shared(smbuf);

        if (threadIdx.x == 0) {
            unsigned long long pol;
            asm("createpolicy.fractional.L2::evict_first.b64 %0, 1.0;" : "=l"(pol));
            for (unsigned c = blockIdx.x; c < nch; c += FILL_BLOCKS) {
                char* dst = (char*)out + (size_t)c * FILL_CHUNK;
                asm volatile(
                    "cp.async.bulk.global.shared::cta.bulk_group.L2::cache_hint "
                    "[%0], [%1], %2, %3;"
                    :: "l"(dst), "r"(saddr), "r"((unsigned)FILL_CHUNK), "l"(pol)
                    : "memory");
            }
            asm volatile("cp.async.bulk.commit_group;" ::: "memory");
            asm volatile("cp.async.bulk.wait_group 0;" ::: "memory");
        }
        size_t tail = bytes % FILL_CHUNK;
        if (tail && blockIdx.x == 0) {
            char* p = (char*)out + bytes - tail;
            for (size_t i = threadIdx.x * 4; i + 3 < tail; i += 1024)
                *(float*)(p + i) = 0.f;
        }
        return;
    }

    // ---- GEMM role: 64 tokens x 64 experts, K-slice of 512 ----
    float* xsT = smbuf;              // [BK][XP] k-major, token minor
    float* wsT = smbuf + BK * XP;    // [BK][XP] k-major, expert minor

    int bid   = blockIdx.x - FILL_BLOCKS;
    int tid   = threadIdx.x;
    int kq    = bid & (KSPLIT - 1);
    int tok0  = (bid >> 2) * BT;
    int kbase = kq * KQ;

    int r = tid >> 2;                // 0..63: token row / expert row
    int c = tid & 3;                 // float4 column group

    const float* xptr = x  + (size_t)(tok0 + r) * D_DIM + kbase;
    const float* wptr = wg + (size_t)r          * D_DIM + kbase;

    unsigned long long acc[4][2];
#pragma unroll
    for (int i = 0; i < 4; i++) { acc[i][0] = 0ull; acc[i][1] = 0ull; }

    int txx = tid & 15;              // expert group: 4*txx
    int tyy = tid >> 4;              // token group:  4*tyy

    // preload tile 0
    float4 a0 = *(const float4*)(xptr + 4 * c);
    float4 a1 = *(const float4*)(xptr + 16 + 4 * c);
    float4 b0 = *(const float4*)(wptr + 4 * c);
    float4 b1 = *(const float4*)(wptr + 16 + 4 * c);

#pragma unroll 1
    for (int t = 0; t < NTILE; t++) {
        // store current tile transposed
        xsT[(4 * c + 0) * XP + r] = a0.x;
        xsT[(4 * c + 1) * XP + r] = a0.y;
        xsT[(4 * c + 2) * XP + r] = a0.z;
        xsT[(4 * c + 3) * XP + r] = a0.w;
        xsT[(4 * c + 16) * XP + r] = a1.x;
        xsT[(4 * c + 17) * XP + r] = a1.y;
        xsT[(4 * c + 18) * XP + r] = a1.z;
        xsT[(4 * c + 19) * XP + r] = a1.w;
        wsT[(4 * c + 0) * XP + r] = b0.x;
        wsT[(4 * c + 1) * XP + r] = b0.y;
        wsT[(4 * c + 2) * XP + r] = b0.z;
        wsT[(4 * c + 3) * XP + r] = b0.w;
        wsT[(4 * c + 16) * XP + r] = b1.x;
        wsT[(4 * c + 17) * XP + r] = b1.y;
        wsT[(4 * c + 18) * XP + r] = b1.z;
        wsT[(4 * c + 19) * XP + r] = b1.w;
        __syncthreads();

        // prefetch next tile into registers (latency hidden under compute)
        if (t + 1 < NTILE) {
            int off = (t + 1) * BK;
            a0 = *(const float4*)(xptr + off + 4 * c);
            a1 = *(const float4*)(xptr + off + 16 + 4 * c);
            b0 = *(const float4*)(wptr + off + 4 * c);
            b1 = *(const float4*)(wptr + off + 16 + 4 * c);
        }

        // compute: 32 kk x (4 tok x 4 exp) via packed f32x2
#pragma unroll
        for (int kk = 0; kk < BK; kk++) {
            float4 xv = *(const float4*)&xsT[kk * XP + 4 * tyy];
            ulonglong2 wp = *(const ulonglong2*)&wsT[kk * XP + 4 * txx];
            unsigned long long x0 = dup2(xv.x), x1 = dup2(xv.y);
            unsigned long long x2 = dup2(xv.z), x3 = dup2(xv.w);
            ffma2(acc[0][0], x0, wp.x); ffma2(acc[0][1], x0, wp.y);
            ffma2(acc[1][0], x1, wp.x); ffma2(acc[1][1], x1, wp.y);
            ffma2(acc[2][0], x2, wp.x); ffma2(acc[2][1], x2, wp.y);
            ffma2(acc[3][0], x3, wp.x); ffma2(acc[3][1], x3, wp.y);
        }
        __syncthreads();
    }

    // epilogue: write partial logits (token-contiguous layout)
#pragma unroll
    for (int i = 0; i < 4; i++) {
        *(float4*)&g_part[tok0 + 4 * tyy + i][kq][4 * txx] =
            make_float4(lo32(acc[i][0]), hi32(acc[i][0]),
                        lo32(acc[i][1]), hi32(acc[i][1]));
    }
}

// ---------------- Kernel B: sum 4 K-parts + top2 + softmax ------------------
__global__ void __launch_bounds__(256) top2_kernel()
{
    int t = blockIdx.x * 256 + threadIdx.x;    // token id
    const float4* pp = (const float4*)&g_part[t][0][0];   // 64 float4, contiguous

    float v0 = -3.4e38f, v1 = -3.4e38f;
    int e0 = 0, e1 = 0;
#pragma unroll
    for (int i = 0; i < N_EXP / 4; i++) {
        float4 a = pp[i], b = pp[16 + i], cc = pp[32 + i], d = pp[48 + i];
        float s[4] = { ((a.x + b.x) + cc.x) + d.x,
                       ((a.y + b.y) + cc.y) + d.y,
                       ((a.z + b.z) + cc.z) + d.z,
                       ((a.w + b.w) + cc.w) + d.w };
#pragma unroll
        for (int j = 0; j < 4; j++) {
            float v = s[j];
            int   e = 4 * i + j;
            if (v > v0)      { v1 = v0; e1 = e0; v0 = v; e0 = e; }
            else if (v > v1) { v1 = v;  e1 = e; }
        }
    }
    float rr = expf(v1 - v0);
    float q0 = 1.f / (1.f + rr);
    float q1 = rr * q0;
    g_te[2 * t]     = e0;
    g_te[2 * t + 1] = e1;
    g_tw[2 * t]     = q0;
    g_tw[2 * t + 1] = q1;
}

// ---------------- Kernel C: order-exact capacity assignment -----------------
// 64 CTAs (one per expert) x 512 threads; each thread owns 16 contiguous
// attempts; block-wide exclusive scan gives exact sequential slots.
__global__ void __launch_bounds__(512) assign_kernel(float* __restrict__ out)
{
    int e    = blockIdx.x;            // expert 0..63
    int tid  = threadIdx.x;
    int lane = tid & 31;
    int wid  = tid >> 5;              // 0..15

    int ids[16];
    const int4* te4 = (const int4*)g_te;
#pragma unroll
    for (int k = 0; k < 4; k++) {
        int4 v = te4[tid * 4 + k];
        ids[4 * k + 0] = v.x; ids[4 * k + 1] = v.y;
        ids[4 * k + 2] = v.z; ids[4 * k + 3] = v.w;
    }

    int cnt = 0;
#pragma unroll
    for (int k = 0; k < 16; k++) cnt += (ids[k] == e);

    int c = cnt;
#pragma unroll
    for (int o = 1; o < 32; o <<= 1) {
        int n = __shfl_up_sync(0xffffffffu, c, o);
        if (lane >= o) c += n;
    }
    __shared__ int wsum[16];
    if (lane == 31) wsum[wid] = c;
    __syncthreads();
    if (wid == 0 && lane < 16) {
        int v = wsum[lane];
#pragma unroll
        for (int o = 1; o < 16; o <<= 1) {
            int n = __shfl_up_sync(0xffffu, v, o);
            if (lane >= o) v += n;
        }
        wsum[lane] = v;
    }
    __syncthreads();
    int prefix = c - cnt + (wid ? wsum[wid - 1] : 0);
    int total  = wsum[15];

    float* cb = out + N_EXP;
    float* mk = out + N_EXP + TEC;
    int slot = prefix;
#pragma unroll
    for (int k = 0; k < 16; k++) {
        if (ids[k] == e) {
            if (slot < CAP) {
                int a = tid * 16 + k;
                int t = a >> 1;
                size_t idx = (size_t)t * (N_EXP * CAP) + (size_t)e * CAP + slot;
                cb[idx] = g_tw[a];
                mk[idx] = 1.0f;
            }
            slot++;
        }
    }

    if (tid == 0)
        out[e] = (float)(total < CAP ? total : CAP);
}

extern "C" void kernel_launch(void* const* d_in, const int* in_sizes, int n_in,
                              void* d_out, int out_size)
{
    const float* x  = (const float*)d_in[0];
    const float* wg = (const float*)d_in[1];
    float* out = (float*)d_out;

    gemm_fill_kernel<<<FILL_BLOCKS + GEMM_BLOCKS, 256>>>(x, wg, out, out_size);
    top2_kernel<<<T_TOK / 256, 256>>>();
    assign_kernel<<<N_EXP, 512>>>(out);
}